// round 7
// baseline (speedup 1.0000x reference)
#include <cuda_runtime.h>
#include <cstdint>
#include <cstddef>

// ---------------------------------------------------------------------------
// ParallelMoELinear: out[t,:] = tokens[t,:] @ W[e(t)] + bias[e(t)]
// E=8, T=4096, D_IN=1024, D_OUT=4096, 512 tokens/expert (sorted).
// sm_100 legacy tensor path (tcgen05 unavailable at this compile target).
// R7: persistent CTAs. R4->R6 established the legacy-HMMA ceiling (~58% of
// ncu's tensor reference, tensor-busy invariant ~129us) -- concurrency beyond
// 2 CTAs/SM buys nothing. Remaining 89us is tail + refill + epilogue. Launch
// exactly 296 CTAs (=2/SM), each loops over 1024/296 tiles: no wave
// quantization (was 3.46 waves), epilogue overlaps next tile's loads.
// Config is the best-measured R5 shape: 256 thr, 64x32 warp tiles, 3 stages.
// A pre-rounded tf32(RN) * (1+3.38e-4) cancels raw-W truncation bias
// (validated R4-R6: rel_err 3.03e-4).
// ---------------------------------------------------------------------------
static constexpr int D_IN  = 1024;
static constexpr int D_OUT = 4096;
static constexpr int T_TOK = 4096;

static constexpr int BM = 128;
static constexpr int BN = 128;
static constexpr int BK = 32;
static constexpr int NSTAGE = 3;
static constexpr int NKT = D_IN / BK;       // 32
static constexpr int NTHREADS = 256;        // 8 warps: 2 (M) x 4 (N), 64x32 tiles
static constexpr int NTILES  = (T_TOK / BM) * (D_OUT / BN);   // 1024
static constexpr int NCTAS   = 296;         // 2 per SM x 148 SMs

// SMEM geometry (word = 4B):
//  A tile: [BM][AROW_W], AROW_W = 36 (32 data + 4 pad)
//    -> LDSM row stride 144B == 4 mod 32 words: conflict-free ldmatrix.
//  B tile: [BK][BROW_W], BROW_W = 136 (128 data + 8 pad)
//    -> scalar B-frag banks = 8*(lane%4) + lane/4: all 32 distinct.
static constexpr int AROW_W = 36;
static constexpr int BROW_W = 136;
static constexpr uint32_t A_STAGE_B = BM * AROW_W * 4;        // 18432
static constexpr uint32_t B_STAGE_B = BK * BROW_W * 4;        // 17408
static constexpr uint32_t SMEM_B0   = NSTAGE * A_STAGE_B;     // 55296
static constexpr uint32_t SMEM_TOTAL = SMEM_B0 + NSTAGE * B_STAGE_B; // 107520

// Scratch for pre-rounded A (16 MB).
__device__ float g_a_tf32[(size_t)T_TOK * D_IN];

// ---------------------------------------------------------------------------
// PTX helpers (sm_80+)
// ---------------------------------------------------------------------------
__device__ __forceinline__ uint32_t smem_to_u32(const void* p) {
    uint32_t a;
    asm("{ .reg .u64 t; cvta.to.shared.u64 t, %1; cvt.u32.u64 %0, t; }"
        : "=r"(a) : "l"(p));
    return a;
}

#define CP_ASYNC_16(dst, src) \
    asm volatile("cp.async.cg.shared.global [%0], [%1], 16;" \
        :: "r"(dst), "l"(src) : "memory")
#define CP_ASYNC_COMMIT() \
    asm volatile("cp.async.commit_group;" ::: "memory")
#define CP_ASYNC_WAIT_GROUP(n) \
    asm volatile("cp.async.wait_group %0;" :: "n"(n) : "memory")

#define LDSM_X4(r, addr) \
    asm volatile("ldmatrix.sync.aligned.m8n8.x4.shared.b16 {%0,%1,%2,%3}, [%4];" \
        : "=r"((r)[0]), "=r"((r)[1]), "=r"((r)[2]), "=r"((r)[3]) \
        : "r"(addr))

#define LDS32(r, addr) \
    asm volatile("ld.shared.b32 %0, [%1];" : "=r"(r) : "r"(addr))

#define CVT_TF32(x) asm volatile("cvt.rna.tf32.f32 %0, %0;" : "+r"(x))

#define MMA_TF32(d, a, b) \
    asm volatile( \
        "mma.sync.aligned.m16n8k8.row.col.f32.tf32.tf32.f32 " \
        "{%0,%1,%2,%3}, {%4,%5,%6,%7}, {%8,%9}, {%0,%1,%2,%3};" \
        : "+f"((d)[0]), "+f"((d)[1]), "+f"((d)[2]), "+f"((d)[3]) \
        : "r"((a)[0]), "r"((a)[1]), "r"((a)[2]), "r"((a)[3]), \
          "r"((b)[0]), "r"((b)[1]))

// ---------------------------------------------------------------------------
// Prepass: A -> tf32(RN) * (1 + 2^-11*ln2), cancels W-truncation bias.
// ---------------------------------------------------------------------------
__global__ void __launch_bounds__(256)
a_round_kernel(const float* __restrict__ a_in) {
    const size_t i = ((size_t)blockIdx.x * 256 + threadIdx.x) * 4;
    float4 v = *reinterpret_cast<const float4*>(a_in + i);
    const float s = 1.000338f;
    uint32_t x0 = __float_as_uint(v.x * s);
    uint32_t x1 = __float_as_uint(v.y * s);
    uint32_t x2 = __float_as_uint(v.z * s);
    uint32_t x3 = __float_as_uint(v.w * s);
    CVT_TF32(x0); CVT_TF32(x1); CVT_TF32(x2); CVT_TF32(x3);
    float4 o;
    o.x = __uint_as_float(x0); o.y = __uint_as_float(x1);
    o.z = __uint_as_float(x2); o.w = __uint_as_float(x3);
    *reinterpret_cast<float4*>(g_a_tf32 + i) = o;
}

// ---------------------------------------------------------------------------
// Persistent GEMM kernel: 296 CTAs, each grid-strides over 1024 tiles.
// ---------------------------------------------------------------------------
__global__ void __launch_bounds__(NTHREADS, 2)
moe_tf32_mma_kernel(const float* __restrict__ W,
                    const float* __restrict__ bias,
                    const int* __restrict__ experts,
                    float* __restrict__ out) {
    extern __shared__ char smem[];
    const uint32_t sb = smem_to_u32(smem);

    const int tid  = threadIdx.x;
    const int lane = tid & 31;
    const int wid  = tid >> 5;
    const int warp_m = wid & 1;       // 2 warps in M -> 64-row warp tiles
    const int warp_n = wid >> 1;      // 4 warps in N -> 32-col warp tiles

    // per-thread invariant pieces of cp.async addressing
    const uint32_t a_dst = (uint32_t)((tid >> 3) * (AROW_W * 4) + (tid & 7) * 16);
    const uint32_t b_dst = (uint32_t)((tid >> 5) * (BROW_W * 4) + (tid & 31) * 16);
    const size_t a_thr_off = (size_t)(tid >> 3) * D_IN + (tid & 7) * 4;
    const size_t b_thr_off = (size_t)(tid >> 5) * D_OUT + (tid & 31) * 4;
    static constexpr int A_GSTRIDE = 32 * D_IN;          // id += 256 -> +32 rows
    static constexpr uint32_t A_SSTRIDE = 32 * AROW_W * 4;
    static constexpr int B_GSTRIDE = 8 * D_OUT;          // id += 256 -> +8 k-rows
    static constexpr uint32_t B_SSTRIDE = 8 * BROW_W * 4;

    // ldmatrix per-thread offset (proven mapping)
    const uint32_t a_toff =
        (uint32_t)(((lane & 7) + ((lane >> 3) & 1) * 8) * (AROW_W * 4) +
                   (lane >> 4) * 16);
    // B scalar fragment: b0 = Bs[k = lane%4][n = lane/4]
    const uint32_t b_toff =
        (uint32_t)((lane & 3) * (BROW_W * 4) + (lane >> 2) * 4);

    for (int t = blockIdx.x; t < NTILES; t += NCTAS) {
        const int n_base = (t & 31) * BN;
        const int m_base = (t >> 5) * BM;
        const int e = experts[m_base];    // uniform in tile (128 | 512)

        const float* a_src = g_a_tf32 + (size_t)m_base * D_IN + a_thr_off;
        const float* b_src = W + (size_t)e * D_IN * D_OUT + n_base + b_thr_off;

        float acc[4][4][4];
#pragma unroll
        for (int i = 0; i < 4; i++)
#pragma unroll
            for (int j = 0; j < 4; j++)
#pragma unroll
                for (int q = 0; q < 4; q++) acc[i][j][q] = 0.0f;

        auto load_stage = [&](int st, int kt) {
            const uint32_t as = sb + (uint32_t)st * A_STAGE_B + a_dst;
            const uint32_t bs = sb + SMEM_B0 + (uint32_t)st * B_STAGE_B + b_dst;
            const float* ag = a_src + kt * BK;
            const float* bg = b_src + (size_t)kt * BK * D_OUT;
#pragma unroll
            for (int i = 0; i < 4; i++)
                CP_ASYNC_16(as + (uint32_t)i * A_SSTRIDE, ag + (size_t)i * A_GSTRIDE);
#pragma unroll
            for (int i = 0; i < 4; i++)
                CP_ASYNC_16(bs + (uint32_t)i * B_SSTRIDE, bg + (size_t)i * B_GSTRIDE);
        };

        // Protect SMEM reuse: all warps must be done reading the previous
        // tile's stages before this tile's prologue overwrites them.
        __syncthreads();

        // Prologue: 2 stages in flight.
        load_stage(0, 0); CP_ASYNC_COMMIT();
        load_stage(1, 1); CP_ASYNC_COMMIT();

        // ---- mainloop ----
        for (int i = 0; i < NKT; i++) {
            if (i < NKT - 1) { CP_ASYNC_WAIT_GROUP(1); } else { CP_ASYNC_WAIT_GROUP(0); }
            __syncthreads();

            if (i + 2 < NKT) {
                load_stage((i + 2) % NSTAGE, i + 2);
                CP_ASYNC_COMMIT();
            }

            const int st = i % NSTAGE;
            const uint32_t abase = sb + (uint32_t)st * A_STAGE_B +
                                   (uint32_t)(warp_m * 64 * (AROW_W * 4)) + a_toff;
            const uint32_t bbase = sb + SMEM_B0 + (uint32_t)st * B_STAGE_B +
                                   (uint32_t)(warp_n * 32 * 4) + b_toff;

#pragma unroll
            for (int s = 0; s < BK / 8; s++) {          // 4 k-steps of 8
                uint32_t a[4][4];
#pragma unroll
                for (int im = 0; im < 4; im++)
                    LDSM_X4(a[im], abase + (uint32_t)(im * 16 * (AROW_W * 4) + s * 32));
                uint32_t b[4][2];
#pragma unroll
                for (int jn = 0; jn < 4; jn++) {
                    const uint32_t ba = bbase + (uint32_t)(jn * 32 + s * 8 * (BROW_W * 4));
                    LDS32(b[jn][0], ba);
                    LDS32(b[jn][1], ba + 4 * (BROW_W * 4));
                }
#pragma unroll
                for (int im = 0; im < 4; im++)
#pragma unroll
                    for (int jn = 0; jn < 4; jn++)
                        MMA_TF32(acc[im][jn], a[im], b[jn]);
            }
        }

        // ---- epilogue: add bias, store float2 pairs ----
        const float* be = bias + (size_t)e * D_OUT + n_base + warp_n * 32;
        const int row0 = m_base + warp_m * 64 + (lane >> 2);
        const int col0 = n_base + warp_n * 32 + (lane & 3) * 2;

#pragma unroll
        for (int jn = 0; jn < 4; jn++) {
            const float2 bb = *reinterpret_cast<const float2*>(be + jn * 8 + (lane & 3) * 2);
#pragma unroll
            for (int im = 0; im < 4; im++) {
                const int r = row0 + im * 16;
                float2 v0 = make_float2(acc[im][jn][0] + bb.x, acc[im][jn][1] + bb.y);
                float2 v1 = make_float2(acc[im][jn][2] + bb.x, acc[im][jn][3] + bb.y);
                *reinterpret_cast<float2*>(out + (size_t)r * D_OUT + col0 + jn * 8) = v0;
                *reinterpret_cast<float2*>(out + (size_t)(r + 8) * D_OUT + col0 + jn * 8) = v1;
            }
        }
    }
}

// ---------------------------------------------------------------------------
// Launch. Inputs (metadata order): sorted_tokens f32[4096,1024],
// kernel f32[8,1024,4096], bias f32[8,4096], group_sizes i32[8],
// sorted_experts i32[4096]. Output f32[4096,4096].
// ---------------------------------------------------------------------------
extern "C" void kernel_launch(void* const* d_in, const int* in_sizes, int n_in,
                              void* d_out, int out_size) {
    const float* tokens  = (const float*)d_in[0];
    const float* W       = (const float*)d_in[1];
    const float* bias    = (const float*)d_in[2];
    const int*   experts = (const int*)d_in[4];   // d_in[3] = group_sizes (unused)
    float* out = (float*)d_out;

    // Prepass: 4M floats, one float4 per thread.
    a_round_kernel<<<(T_TOK * D_IN) / (256 * 4), 256>>>(tokens);

    cudaFuncSetAttribute(moe_tf32_mma_kernel,
                         cudaFuncAttributeMaxDynamicSharedMemorySize, SMEM_TOTAL);
    moe_tf32_mma_kernel<<<NCTAS, NTHREADS, SMEM_TOTAL>>>(W, bias, experts, out);
}

// round 8
// speedup vs baseline: 1.0022x; 1.0022x over previous
#include <cuda_runtime.h>
#include <cstdint>
#include <cstddef>

// ---------------------------------------------------------------------------
// ParallelMoELinear: out[t,:] = tokens[t,:] @ W[e(t)] + bias[e(t)]
// E=8, T=4096, D_IN=1024, D_OUT=4096, 512 tokens/expert (sorted).
// sm_100 legacy tensor path (tcgen05 unavailable at this compile target).
// R8: persistent CTAs with a NON-DRAINING cross-tile cp.async ring. R7 showed
// per-tile pipeline drain+refill costs more than the wave tail it removes;
// here the 3-stage ring streams over the CTA's whole chunk sequence
// (ntiles*32 chunks) so tile boundaries cost only the register epilogue.
// Prepass removed: HW truncates both A and W to tf32; the combined mean bias
// (2 x 3.38e-4, single-matrix factor validated R4-R7) is cancelled by scaling
// acc by 1.000676 in the epilogue. Expected rel_err ~4-6e-4.
// ---------------------------------------------------------------------------
static constexpr int D_IN  = 1024;
static constexpr int D_OUT = 4096;
static constexpr int T_TOK = 4096;

static constexpr int BM = 128;
static constexpr int BN = 128;
static constexpr int BK = 32;
static constexpr int NSTAGE = 3;
static constexpr int NKT = D_IN / BK;       // 32 chunks per tile
static constexpr int NTHREADS = 256;        // 8 warps: 2 (M) x 4 (N), 64x32 tiles
static constexpr int NTILES  = (T_TOK / BM) * (D_OUT / BN);   // 1024
static constexpr int NCTAS   = 296;         // 2 per SM x 148 SMs

static constexpr float OUT_SCALE = 1.000676f;   // (1+3.38e-4)^2: A+W truncation bias

// SMEM geometry (word = 4B):
//  A tile: [BM][AROW_W], AROW_W = 36 (32 data + 4 pad)
//    -> LDSM row stride 144B == 4 mod 32 words: conflict-free ldmatrix.
//  B tile: [BK][BROW_W], BROW_W = 136 (128 data + 8 pad)
//    -> scalar B-frag banks = 8*(lane%4) + lane/4: all 32 distinct.
static constexpr int AROW_W = 36;
static constexpr int BROW_W = 136;
static constexpr uint32_t A_STAGE_B = BM * AROW_W * 4;        // 18432
static constexpr uint32_t B_STAGE_B = BK * BROW_W * 4;        // 17408
static constexpr uint32_t SMEM_B0   = NSTAGE * A_STAGE_B;     // 55296
static constexpr uint32_t SMEM_TOTAL = SMEM_B0 + NSTAGE * B_STAGE_B; // 107520

// ---------------------------------------------------------------------------
// PTX helpers (sm_80+)
// ---------------------------------------------------------------------------
__device__ __forceinline__ uint32_t smem_to_u32(const void* p) {
    uint32_t a;
    asm("{ .reg .u64 t; cvta.to.shared.u64 t, %1; cvt.u32.u64 %0, t; }"
        : "=r"(a) : "l"(p));
    return a;
}

#define CP_ASYNC_16(dst, src) \
    asm volatile("cp.async.cg.shared.global [%0], [%1], 16;" \
        :: "r"(dst), "l"(src) : "memory")
#define CP_ASYNC_COMMIT() \
    asm volatile("cp.async.commit_group;" ::: "memory")
#define CP_ASYNC_WAIT_GROUP(n) \
    asm volatile("cp.async.wait_group %0;" :: "n"(n) : "memory")

#define LDSM_X4(r, addr) \
    asm volatile("ldmatrix.sync.aligned.m8n8.x4.shared.b16 {%0,%1,%2,%3}, [%4];" \
        : "=r"((r)[0]), "=r"((r)[1]), "=r"((r)[2]), "=r"((r)[3]) \
        : "r"(addr))

#define LDS32(r, addr) \
    asm volatile("ld.shared.b32 %0, [%1];" : "=r"(r) : "r"(addr))

#define MMA_TF32(d, a, b) \
    asm volatile( \
        "mma.sync.aligned.m16n8k8.row.col.f32.tf32.tf32.f32 " \
        "{%0,%1,%2,%3}, {%4,%5,%6,%7}, {%8,%9}, {%0,%1,%2,%3};" \
        : "+f"((d)[0]), "+f"((d)[1]), "+f"((d)[2]), "+f"((d)[3]) \
        : "r"((a)[0]), "r"((a)[1]), "r"((a)[2]), "r"((a)[3]), \
          "r"((b)[0]), "r"((b)[1]))

// ---------------------------------------------------------------------------
// Persistent GEMM kernel: 296 CTAs, continuous chunk stream (no drain).
// ---------------------------------------------------------------------------
__global__ void __launch_bounds__(NTHREADS, 2)
moe_tf32_mma_kernel(const float* __restrict__ tokens,
                    const float* __restrict__ W,
                    const float* __restrict__ bias,
                    const int* __restrict__ experts,
                    float* __restrict__ out) {
    extern __shared__ char smem[];
    const uint32_t sb = smem_to_u32(smem);

    const int tid  = threadIdx.x;
    const int lane = tid & 31;
    const int wid  = tid >> 5;
    const int warp_m = wid & 1;       // 2 warps in M -> 64-row warp tiles
    const int warp_n = wid >> 1;      // 4 warps in N -> 32-col warp tiles

    // per-thread invariant pieces of cp.async addressing
    const uint32_t a_dst = (uint32_t)((tid >> 3) * (AROW_W * 4) + (tid & 7) * 16);
    const uint32_t b_dst = (uint32_t)((tid >> 5) * (BROW_W * 4) + (tid & 31) * 16);
    const size_t a_thr_off = (size_t)(tid >> 3) * D_IN + (tid & 7) * 4;
    const size_t b_thr_off = (size_t)(tid >> 5) * D_OUT + (tid & 31) * 4;
    static constexpr int A_GSTRIDE = 32 * D_IN;          // id += 256 -> +32 rows
    static constexpr uint32_t A_SSTRIDE = 32 * AROW_W * 4;
    static constexpr int B_GSTRIDE = 8 * D_OUT;          // id += 256 -> +8 k-rows
    static constexpr uint32_t B_SSTRIDE = 8 * BROW_W * 4;

    // ldmatrix per-thread offset (proven mapping)
    const uint32_t a_toff =
        (uint32_t)(((lane & 7) + ((lane >> 3) & 1) * 8) * (AROW_W * 4) +
                   (lane >> 4) * 16);
    // B scalar fragment: b0 = Bs[k = lane%4][n = lane/4]
    const uint32_t b_toff =
        (uint32_t)((lane & 3) * (BROW_W * 4) + (lane >> 2) * 4);

    // Number of tiles this CTA owns (grid-stride over 1024 tiles).
    const int ntiles = (NTILES - blockIdx.x + NCTAS - 1) / NCTAS;   // 3 or 4
    const int total  = ntiles * NKT;

    // Resolve tile lt (local index) -> global bases + source pointers.
    auto tile_desc = [&](int lt, int& m_b, int& n_b, int& te,
                         const float*& as, const float*& bs) {
        const int t = blockIdx.x + lt * NCTAS;
        n_b = (t & 31) * BN;
        m_b = (t >> 5) * BM;
        te  = experts[m_b];                 // uniform in tile (128 | 512)
        as  = tokens + (size_t)m_b * D_IN + a_thr_off;
        bs  = W + (size_t)te * D_IN * D_OUT + n_b + b_thr_off;
    };

    // Load-side state (tile whose chunks are being fetched)
    int lm, ln, le;
    const float *la_src, *lb_src;
    tile_desc(0, lm, ln, le, la_src, lb_src);
    // Compute-side state (tile whose chunks are being consumed / epilogued)
    int cm = lm, cn = ln, ce = le;
    int ctile = 0;

    auto load_stage = [&](int st, const float* ag, const float* bg) {
        const uint32_t as = sb + (uint32_t)st * A_STAGE_B + a_dst;
        const uint32_t bs = sb + SMEM_B0 + (uint32_t)st * B_STAGE_B + b_dst;
#pragma unroll
        for (int i = 0; i < 4; i++)
            CP_ASYNC_16(as + (uint32_t)i * A_SSTRIDE, ag + (size_t)i * A_GSTRIDE);
#pragma unroll
        for (int i = 0; i < 4; i++)
            CP_ASYNC_16(bs + (uint32_t)i * B_SSTRIDE, bg + (size_t)i * B_GSTRIDE);
    };

    float acc[4][4][4];
#pragma unroll
    for (int i = 0; i < 4; i++)
#pragma unroll
        for (int j = 0; j < 4; j++)
#pragma unroll
            for (int q = 0; q < 4; q++) acc[i][j][q] = 0.0f;

    // Prologue: chunks 0 and 1 of tile 0.
    load_stage(0, la_src, lb_src);                       CP_ASYNC_COMMIT();
    load_stage(1, la_src + BK, lb_src + (size_t)BK * D_OUT); CP_ASYNC_COMMIT();

    // ---- continuous mainloop over all chunks of all owned tiles ----
    for (int c = 0; c < total; c++) {
        if (c < total - 1) { CP_ASYNC_WAIT_GROUP(1); } else { CP_ASYNC_WAIT_GROUP(0); }
        __syncthreads();

        const int cl = c + 2;                 // chunk to fetch this iteration
        if (cl < total) {
            const int kt = cl & (NKT - 1);
            if (kt == 0)                      // crossing into next load tile
                tile_desc(cl >> 5, lm, ln, le, la_src, lb_src);
            load_stage(cl % NSTAGE, la_src + kt * BK,
                       lb_src + (size_t)kt * BK * D_OUT);
            CP_ASYNC_COMMIT();
        }

        const int st = c % NSTAGE;
        const uint32_t abase = sb + (uint32_t)st * A_STAGE_B +
                               (uint32_t)(warp_m * 64 * (AROW_W * 4)) + a_toff;
        const uint32_t bbase = sb + SMEM_B0 + (uint32_t)st * B_STAGE_B +
                               (uint32_t)(warp_n * 32 * 4) + b_toff;

#pragma unroll
        for (int s = 0; s < BK / 8; s++) {          // 4 k-steps of 8
            uint32_t a[4][4];
#pragma unroll
            for (int im = 0; im < 4; im++)
                LDSM_X4(a[im], abase + (uint32_t)(im * 16 * (AROW_W * 4) + s * 32));
            uint32_t b[4][2];
#pragma unroll
            for (int jn = 0; jn < 4; jn++) {
                const uint32_t ba = bbase + (uint32_t)(jn * 32 + s * 8 * (BROW_W * 4));
                LDS32(b[jn][0], ba);
                LDS32(b[jn][1], ba + 4 * (BROW_W * 4));
            }
#pragma unroll
            for (int im = 0; im < 4; im++)
#pragma unroll
                for (int jn = 0; jn < 4; jn++)
                    MMA_TF32(acc[im][jn], a[im], b[jn]);
        }

        // ---- tile finished: register epilogue (no SMEM, no sync) ----
        if ((c & (NKT - 1)) == NKT - 1) {
            const float* be = bias + (size_t)ce * D_OUT + cn + warp_n * 32;
            const int row0 = cm + warp_m * 64 + (lane >> 2);
            const int col0 = cn + warp_n * 32 + (lane & 3) * 2;
#pragma unroll
            for (int jn = 0; jn < 4; jn++) {
                const float2 bb =
                    *reinterpret_cast<const float2*>(be + jn * 8 + (lane & 3) * 2);
#pragma unroll
                for (int im = 0; im < 4; im++) {
                    const int r = row0 + im * 16;
                    float2 v0 = make_float2(fmaf(acc[im][jn][0], OUT_SCALE, bb.x),
                                            fmaf(acc[im][jn][1], OUT_SCALE, bb.y));
                    float2 v1 = make_float2(fmaf(acc[im][jn][2], OUT_SCALE, bb.x),
                                            fmaf(acc[im][jn][3], OUT_SCALE, bb.y));
                    *reinterpret_cast<float2*>(out + (size_t)r * D_OUT + col0 + jn * 8) = v0;
                    *reinterpret_cast<float2*>(out + (size_t)(r + 8) * D_OUT + col0 + jn * 8) = v1;
#pragma unroll
                    for (int q = 0; q < 4; q++) acc[im][jn][q] = 0.0f;
                }
            }
            // advance compute-tile descriptor
            ctile++;
            if (ctile < ntiles) {
                const float *dummy_a, *dummy_b;
                tile_desc(ctile, cm, cn, ce, dummy_a, dummy_b);
            }
        }
    }
}

// ---------------------------------------------------------------------------
// Launch. Inputs (metadata order): sorted_tokens f32[4096,1024],
// kernel f32[8,1024,4096], bias f32[8,4096], group_sizes i32[8],
// sorted_experts i32[4096]. Output f32[4096,4096].
// ---------------------------------------------------------------------------
extern "C" void kernel_launch(void* const* d_in, const int* in_sizes, int n_in,
                              void* d_out, int out_size) {
    const float* tokens  = (const float*)d_in[0];
    const float* W       = (const float*)d_in[1];
    const float* bias    = (const float*)d_in[2];
    const int*   experts = (const int*)d_in[4];   // d_in[3] = group_sizes (unused)
    float* out = (float*)d_out;

    cudaFuncSetAttribute(moe_tf32_mma_kernel,
                         cudaFuncAttributeMaxDynamicSharedMemorySize, SMEM_TOTAL);
    moe_tf32_mma_kernel<<<NCTAS, NTHREADS, SMEM_TOTAL>>>(tokens, W, bias, experts, out);
}

// round 9
// speedup vs baseline: 1.1468x; 1.1442x over previous
#include <cuda_runtime.h>
#include <cstdint>
#include <cstddef>

// ---------------------------------------------------------------------------
// ParallelMoELinear: out[t,:] = tokens[t,:] @ W[e(t)] + bias[e(t)]
// E=8, T=4096, D_IN=1024, D_OUT=4096, 512 tokens/expert (sorted).
// sm_100 legacy tensor path (tcgen05 unavailable at this compile target).
// R9: consolidation. R5's config is the measured optimum of the mma.sync
// design space (218us; 1024 CTAs, 2 CTAs/SM, 256 thr, 64x32 warp tiles,
// 3-stage cp.async). Persistent variants (R7/R8) regressed -- abandoned.
// This round: R5 EXACTLY, minus the A-prepass kernel. Both A and W are
// truncated to tf32 by the MMA hardware; the combined deterministic downward
// bias (2 x 2^-11*ln2) is cancelled by scaling acc by 1.000676 in the
// epilogue (validated R8: rel_err 3.12e-4). Saves one graph node + a 32MB
// DRAM round-trip inside the timed region.
// ---------------------------------------------------------------------------
static constexpr int D_IN  = 1024;
static constexpr int D_OUT = 4096;
static constexpr int T_TOK = 4096;

static constexpr int BM = 128;
static constexpr int BN = 128;
static constexpr int BK = 32;
static constexpr int NSTAGE = 3;
static constexpr int NKT = D_IN / BK;       // 32
static constexpr int NTHREADS = 256;        // 8 warps: 2 (M) x 4 (N), 64x32 tiles

static constexpr float OUT_SCALE = 1.000676f;   // (1+3.38e-4)^2: A+W truncation bias

// SMEM geometry (word = 4B):
//  A tile: [BM][AROW_W], AROW_W = 36 (32 data + 4 pad)
//    -> LDSM row stride 144B == 4 mod 32 words: conflict-free ldmatrix.
//  B tile: [BK][BROW_W], BROW_W = 136 (128 data + 8 pad)
//    -> scalar B-frag banks = 8*(lane%4) + lane/4: all 32 distinct.
static constexpr int AROW_W = 36;
static constexpr int BROW_W = 136;
static constexpr uint32_t A_STAGE_B = BM * AROW_W * 4;        // 18432
static constexpr uint32_t B_STAGE_B = BK * BROW_W * 4;        // 17408
static constexpr uint32_t SMEM_B0   = NSTAGE * A_STAGE_B;     // 55296
static constexpr uint32_t SMEM_TOTAL = SMEM_B0 + NSTAGE * B_STAGE_B; // 107520

// ---------------------------------------------------------------------------
// PTX helpers (sm_80+)
// ---------------------------------------------------------------------------
__device__ __forceinline__ uint32_t smem_to_u32(const void* p) {
    uint32_t a;
    asm("{ .reg .u64 t; cvta.to.shared.u64 t, %1; cvt.u32.u64 %0, t; }"
        : "=r"(a) : "l"(p));
    return a;
}

#define CP_ASYNC_16(dst, src) \
    asm volatile("cp.async.cg.shared.global [%0], [%1], 16;" \
        :: "r"(dst), "l"(src) : "memory")
#define CP_ASYNC_COMMIT() \
    asm volatile("cp.async.commit_group;" ::: "memory")
#define CP_ASYNC_WAIT_GROUP(n) \
    asm volatile("cp.async.wait_group %0;" :: "n"(n) : "memory")

#define LDSM_X4(r, addr) \
    asm volatile("ldmatrix.sync.aligned.m8n8.x4.shared.b16 {%0,%1,%2,%3}, [%4];" \
        : "=r"((r)[0]), "=r"((r)[1]), "=r"((r)[2]), "=r"((r)[3]) \
        : "r"(addr))

#define LDS32(r, addr) \
    asm volatile("ld.shared.b32 %0, [%1];" : "=r"(r) : "r"(addr))

#define MMA_TF32(d, a, b) \
    asm volatile( \
        "mma.sync.aligned.m16n8k8.row.col.f32.tf32.tf32.f32 " \
        "{%0,%1,%2,%3}, {%4,%5,%6,%7}, {%8,%9}, {%0,%1,%2,%3};" \
        : "+f"((d)[0]), "+f"((d)[1]), "+f"((d)[2]), "+f"((d)[3]) \
        : "r"((a)[0]), "r"((a)[1]), "r"((a)[2]), "r"((a)[3]), \
          "r"((b)[0]), "r"((b)[1]))

// ---------------------------------------------------------------------------
// GEMM kernel (identical to R5 except: A from tokens, scaled epilogue)
// ---------------------------------------------------------------------------
__global__ void __launch_bounds__(NTHREADS, 2)
moe_tf32_mma_kernel(const float* __restrict__ tokens,
                    const float* __restrict__ W,
                    const float* __restrict__ bias,
                    const int* __restrict__ experts,
                    float* __restrict__ out) {
    extern __shared__ char smem[];
    const uint32_t sb = smem_to_u32(smem);

    const int tid  = threadIdx.x;
    const int lane = tid & 31;
    const int wid  = tid >> 5;
    const int warp_m = wid & 1;       // 2 warps in M -> 64-row warp tiles
    const int warp_n = wid >> 1;      // 4 warps in N -> 32-col warp tiles

    const int m_base = blockIdx.y * BM;
    const int n_base = blockIdx.x * BN;
    const int e = experts[m_base];    // uniform within 128-row tile (128 | 512)

    // per-thread cp.async source/dest (advance by constants)
    const float* a_src = tokens + (size_t)m_base * D_IN +
                         (size_t)(tid >> 3) * D_IN + (tid & 7) * 4;
    const float* b_src = W + (size_t)e * D_IN * D_OUT + n_base +
                         (size_t)(tid >> 5) * D_OUT + (tid & 31) * 4;
    const uint32_t a_dst = (uint32_t)((tid >> 3) * (AROW_W * 4) + (tid & 7) * 16);
    const uint32_t b_dst = (uint32_t)((tid >> 5) * (BROW_W * 4) + (tid & 31) * 16);
    static constexpr int A_GSTRIDE = 32 * D_IN;          // id += 256 -> +32 rows
    static constexpr uint32_t A_SSTRIDE = 32 * AROW_W * 4;
    static constexpr int B_GSTRIDE = 8 * D_OUT;          // id += 256 -> +8 k-rows
    static constexpr uint32_t B_SSTRIDE = 8 * BROW_W * 4;

    // ldmatrix per-thread offset (proven mapping)
    const uint32_t a_toff =
        (uint32_t)(((lane & 7) + ((lane >> 3) & 1) * 8) * (AROW_W * 4) +
                   (lane >> 4) * 16);
    // B scalar fragment: b0 = Bs[k = lane%4][n = lane/4]
    const uint32_t b_toff =
        (uint32_t)((lane & 3) * (BROW_W * 4) + (lane >> 2) * 4);

    float acc[4][4][4];
#pragma unroll
    for (int i = 0; i < 4; i++)
#pragma unroll
        for (int j = 0; j < 4; j++)
#pragma unroll
            for (int q = 0; q < 4; q++) acc[i][j][q] = 0.0f;

    auto load_stage = [&](int st, int kt) {
        const uint32_t as = sb + (uint32_t)st * A_STAGE_B + a_dst;
        const uint32_t bs = sb + SMEM_B0 + (uint32_t)st * B_STAGE_B + b_dst;
        const float* ag = a_src + kt * BK;
        const float* bg = b_src + (size_t)kt * BK * D_OUT;
#pragma unroll
        for (int i = 0; i < 4; i++)
            CP_ASYNC_16(as + (uint32_t)i * A_SSTRIDE, ag + (size_t)i * A_GSTRIDE);
#pragma unroll
        for (int i = 0; i < 4; i++)
            CP_ASYNC_16(bs + (uint32_t)i * B_SSTRIDE, bg + (size_t)i * B_GSTRIDE);
    };

    // Prologue: 2 stages in flight.
    load_stage(0, 0); CP_ASYNC_COMMIT();
    load_stage(1, 1); CP_ASYNC_COMMIT();

    // ---- mainloop ----
    for (int i = 0; i < NKT; i++) {
        if (i < NKT - 1) { CP_ASYNC_WAIT_GROUP(1); } else { CP_ASYNC_WAIT_GROUP(0); }
        __syncthreads();

        if (i + 2 < NKT) {
            load_stage((i + 2) % NSTAGE, i + 2);
            CP_ASYNC_COMMIT();
        }

        const int st = i % NSTAGE;
        const uint32_t abase = sb + (uint32_t)st * A_STAGE_B +
                               (uint32_t)(warp_m * 64 * (AROW_W * 4)) + a_toff;
        const uint32_t bbase = sb + SMEM_B0 + (uint32_t)st * B_STAGE_B +
                               (uint32_t)(warp_n * 32 * 4) + b_toff;

#pragma unroll
        for (int s = 0; s < BK / 8; s++) {          // 4 k-steps of 8
            uint32_t a[4][4];
#pragma unroll
            for (int im = 0; im < 4; im++)
                LDSM_X4(a[im], abase + (uint32_t)(im * 16 * (AROW_W * 4) + s * 32));
            uint32_t b[4][2];
#pragma unroll
            for (int jn = 0; jn < 4; jn++) {
                const uint32_t ba = bbase + (uint32_t)(jn * 32 + s * 8 * (BROW_W * 4));
                LDS32(b[jn][0], ba);
                LDS32(b[jn][1], ba + 4 * (BROW_W * 4));
            }
#pragma unroll
            for (int im = 0; im < 4; im++)
#pragma unroll
                for (int jn = 0; jn < 4; jn++)
                    MMA_TF32(acc[im][jn], a[im], b[jn]);
        }
    }

    // ---- epilogue: bias-cancel scale + bias, store float2 pairs ----
    const float* be = bias + (size_t)e * D_OUT + n_base + warp_n * 32;
    const int row0 = m_base + warp_m * 64 + (lane >> 2);
    const int col0 = n_base + warp_n * 32 + (lane & 3) * 2;

#pragma unroll
    for (int jn = 0; jn < 4; jn++) {
        const float2 bb = *reinterpret_cast<const float2*>(be + jn * 8 + (lane & 3) * 2);
#pragma unroll
        for (int im = 0; im < 4; im++) {
            const int r = row0 + im * 16;
            float2 v0 = make_float2(fmaf(acc[im][jn][0], OUT_SCALE, bb.x),
                                    fmaf(acc[im][jn][1], OUT_SCALE, bb.y));
            float2 v1 = make_float2(fmaf(acc[im][jn][2], OUT_SCALE, bb.x),
                                    fmaf(acc[im][jn][3], OUT_SCALE, bb.y));
            *reinterpret_cast<float2*>(out + (size_t)r * D_OUT + col0 + jn * 8) = v0;
            *reinterpret_cast<float2*>(out + (size_t)(r + 8) * D_OUT + col0 + jn * 8) = v1;
        }
    }
}

// ---------------------------------------------------------------------------
// Launch. Inputs (metadata order): sorted_tokens f32[4096,1024],
// kernel f32[8,1024,4096], bias f32[8,4096], group_sizes i32[8],
// sorted_experts i32[4096]. Output f32[4096,4096].
// ---------------------------------------------------------------------------
extern "C" void kernel_launch(void* const* d_in, const int* in_sizes, int n_in,
                              void* d_out, int out_size) {
    const float* tokens  = (const float*)d_in[0];
    const float* W       = (const float*)d_in[1];
    const float* bias    = (const float*)d_in[2];
    const int*   experts = (const int*)d_in[4];   // d_in[3] = group_sizes (unused)
    float* out = (float*)d_out;

    cudaFuncSetAttribute(moe_tf32_mma_kernel,
                         cudaFuncAttributeMaxDynamicSharedMemorySize, SMEM_TOTAL);
    dim3 grid(D_OUT / BN, T_TOK / BM);   // (32, 32)
    moe_tf32_mma_kernel<<<grid, NTHREADS, SMEM_TOTAL>>>(tokens, W, bias, experts, out);
}

// round 10
// speedup vs baseline: 1.4188x; 1.2372x over previous
#include <cuda_runtime.h>
#include <cstdint>
#include <cstddef>

// ---------------------------------------------------------------------------
// ParallelMoELinear: out[t,:] = tokens[t,:] @ W[e(t)] + bias[e(t)]
// E=8, T=4096, D_IN=1024, D_OUT=4096, 512 tokens/expert (sorted).
// sm_100 legacy tensor path (tcgen05 unavailable at this compile target).
// R10: mbarrier-skewed pipeline. The per-iteration __syncthreads aligned all
// warps into the same load/MMA phase (R4 1-CTA: 49% tensor; R5 2-CTA with
// independent barriers: 58%). Replace barrier+wait_group with per-stage
// full/empty mbarriers (cp.async.mbarrier.arrive.noinc tracks data arrival;
// per-warp arrive releases a stage) so warps drift and their load bursts
// interleave with other warps' MMAs. Compute core, layouts, and the
// bias-cancel epilogue (OUT_SCALE, validated R8/R9: rel_err 3.12e-4) are
// byte-identical to R9.
// ---------------------------------------------------------------------------
static constexpr int D_IN  = 1024;
static constexpr int D_OUT = 4096;
static constexpr int T_TOK = 4096;

static constexpr int BM = 128;
static constexpr int BN = 128;
static constexpr int BK = 32;
static constexpr int NSTAGE = 3;
static constexpr int NKT = D_IN / BK;       // 32
static constexpr int NTHREADS = 256;        // 8 warps: 2 (M) x 4 (N), 64x32 tiles

static constexpr float OUT_SCALE = 1.000676f;   // (1+3.38e-4)^2: A+W truncation bias

// SMEM geometry (word = 4B):
//  A tile: [BM][AROW_W], AROW_W = 36 (32 data + 4 pad)
//    -> LDSM row stride 144B == 4 mod 32 words: conflict-free ldmatrix.
//  B tile: [BK][BROW_W], BROW_W = 136 (128 data + 8 pad)
//    -> scalar B-frag banks = 8*(lane%4) + lane/4: all 32 distinct.
static constexpr int AROW_W = 36;
static constexpr int BROW_W = 136;
static constexpr uint32_t A_STAGE_B = BM * AROW_W * 4;        // 18432
static constexpr uint32_t B_STAGE_B = BK * BROW_W * 4;        // 17408
static constexpr uint32_t SMEM_B0   = NSTAGE * A_STAGE_B;     // 55296
static constexpr uint32_t SMEM_MBAR = SMEM_B0 + NSTAGE * B_STAGE_B;  // 107520
// full[s] at MBAR + s*16, empty[s] at MBAR + s*16 + 8
static constexpr uint32_t SMEM_TOTAL = SMEM_MBAR + NSTAGE * 16;      // 107568

// ---------------------------------------------------------------------------
// PTX helpers (sm_80+)
// ---------------------------------------------------------------------------
__device__ __forceinline__ uint32_t smem_to_u32(const void* p) {
    uint32_t a;
    asm("{ .reg .u64 t; cvta.to.shared.u64 t, %1; cvt.u32.u64 %0, t; }"
        : "=r"(a) : "l"(p));
    return a;
}

#define CP_ASYNC_16(dst, src) \
    asm volatile("cp.async.cg.shared.global [%0], [%1], 16;" \
        :: "r"(dst), "l"(src) : "memory")

// Arrive-on: this thread's arrival lands on the mbarrier once all its prior
// cp.asyncs complete. .noinc -> arrivals are part of the init count.
#define CP_ASYNC_MBAR_ARRIVE(mbar) \
    asm volatile("cp.async.mbarrier.arrive.noinc.shared.b64 [%0];" \
        :: "r"((uint32_t)(mbar)) : "memory")

#define MBARRIER_INIT(mbar, count) \
    asm volatile("mbarrier.init.shared.b64 [%0], %1;" \
        :: "r"((uint32_t)(mbar)), "r"((uint32_t)(count)) : "memory")

#define MBARRIER_ARRIVE(mbar) \
    asm volatile("mbarrier.arrive.shared.b64 _, [%0];" \
        :: "r"((uint32_t)(mbar)) : "memory")

#define MBARRIER_WAIT_PARITY(mbar_smem_addr, phase_parity) do { \
    uint32_t _mbar = (uint32_t)(mbar_smem_addr); \
    uint32_t _parity = (uint32_t)(phase_parity); \
    uint32_t _done; \
    asm volatile( \
        "{\n\t.reg .pred p;\n\t" \
        "mbarrier.try_wait.parity.acquire.cta.shared::cta.b64 p, [%1], %2;\n\t" \
        "selp.b32 %0, 1, 0, p;\n\t}" \
        : "=r"(_done) : "r"(_mbar), "r"(_parity) : "memory"); \
    if (!_done) { \
        asm volatile( \
            "{\n\t.reg .pred P1;\n\t" \
            "WAIT_LOOP_%=:\n\t" \
            "mbarrier.try_wait.parity.acquire.cta.shared::cta.b64 P1, [%0], %1, 0x989680;\n\t" \
            "@P1 bra.uni WAIT_DONE_%=;\n\t" \
            "bra.uni WAIT_LOOP_%=;\n\t" \
            "WAIT_DONE_%=:\n\t}" \
            :: "r"(_mbar), "r"(_parity) : "memory"); \
    } \
} while (0)

#define LDSM_X4(r, addr) \
    asm volatile("ldmatrix.sync.aligned.m8n8.x4.shared.b16 {%0,%1,%2,%3}, [%4];" \
        : "=r"((r)[0]), "=r"((r)[1]), "=r"((r)[2]), "=r"((r)[3]) \
        : "r"(addr))

#define LDS32(r, addr) \
    asm volatile("ld.shared.b32 %0, [%1];" : "=r"(r) : "r"(addr))

#define MMA_TF32(d, a, b) \
    asm volatile( \
        "mma.sync.aligned.m16n8k8.row.col.f32.tf32.tf32.f32 " \
        "{%0,%1,%2,%3}, {%4,%5,%6,%7}, {%8,%9}, {%0,%1,%2,%3};" \
        : "+f"((d)[0]), "+f"((d)[1]), "+f"((d)[2]), "+f"((d)[3]) \
        : "r"((a)[0]), "r"((a)[1]), "r"((a)[2]), "r"((a)[3]), \
          "r"((b)[0]), "r"((b)[1]))

// ---------------------------------------------------------------------------
// GEMM kernel
// ---------------------------------------------------------------------------
__global__ void __launch_bounds__(NTHREADS, 2)
moe_tf32_mma_kernel(const float* __restrict__ tokens,
                    const float* __restrict__ W,
                    const float* __restrict__ bias,
                    const int* __restrict__ experts,
                    float* __restrict__ out) {
    extern __shared__ char smem[];
    const uint32_t sb = smem_to_u32(smem);

    const int tid  = threadIdx.x;
    const int lane = tid & 31;
    const int wid  = tid >> 5;
    const int warp_m = wid & 1;       // 2 warps in M -> 64-row warp tiles
    const int warp_n = wid >> 1;      // 4 warps in N -> 32-col warp tiles

    const int m_base = blockIdx.y * BM;
    const int n_base = blockIdx.x * BN;
    const int e = experts[m_base];    // uniform within 128-row tile (128 | 512)

    // per-thread cp.async source/dest (advance by constants)
    const float* a_src = tokens + (size_t)m_base * D_IN +
                         (size_t)(tid >> 3) * D_IN + (tid & 7) * 4;
    const float* b_src = W + (size_t)e * D_IN * D_OUT + n_base +
                         (size_t)(tid >> 5) * D_OUT + (tid & 31) * 4;
    const uint32_t a_dst = (uint32_t)((tid >> 3) * (AROW_W * 4) + (tid & 7) * 16);
    const uint32_t b_dst = (uint32_t)((tid >> 5) * (BROW_W * 4) + (tid & 31) * 16);
    static constexpr int A_GSTRIDE = 32 * D_IN;          // id += 256 -> +32 rows
    static constexpr uint32_t A_SSTRIDE = 32 * AROW_W * 4;
    static constexpr int B_GSTRIDE = 8 * D_OUT;          // id += 256 -> +8 k-rows
    static constexpr uint32_t B_SSTRIDE = 8 * BROW_W * 4;

    // ldmatrix per-thread offset (proven mapping)
    const uint32_t a_toff =
        (uint32_t)(((lane & 7) + ((lane >> 3) & 1) * 8) * (AROW_W * 4) +
                   (lane >> 4) * 16);
    // B scalar fragment: b0 = Bs[k = lane%4][n = lane/4]
    const uint32_t b_toff =
        (uint32_t)((lane & 3) * (BROW_W * 4) + (lane >> 2) * 4);

    // mbarrier addresses
    const uint32_t mb = sb + SMEM_MBAR;
    // full[s] = mb + s*16 ; empty[s] = mb + s*16 + 8
    if (tid == 0) {
#pragma unroll
        for (int s = 0; s < NSTAGE; s++) {
            MBARRIER_INIT(mb + s * 16, NTHREADS);   // full: 256 cp.async arrivals
            MBARRIER_INIT(mb + s * 16 + 8, 8);      // empty: 1 per warp
        }
    }
    __syncthreads();   // the only CTA-wide barrier: mbarrier init visibility

    float acc[4][4][4];
#pragma unroll
    for (int i = 0; i < 4; i++)
#pragma unroll
        for (int j = 0; j < 4; j++)
#pragma unroll
            for (int q = 0; q < 4; q++) acc[i][j][q] = 0.0f;

    auto load_stage = [&](int st, int kt) {
        const uint32_t as = sb + (uint32_t)st * A_STAGE_B + a_dst;
        const uint32_t bs = sb + SMEM_B0 + (uint32_t)st * B_STAGE_B + b_dst;
        const float* ag = a_src + kt * BK;
        const float* bg = b_src + (size_t)kt * BK * D_OUT;
#pragma unroll
        for (int i = 0; i < 4; i++)
            CP_ASYNC_16(as + (uint32_t)i * A_SSTRIDE, ag + (size_t)i * A_GSTRIDE);
#pragma unroll
        for (int i = 0; i < 4; i++)
            CP_ASYNC_16(bs + (uint32_t)i * B_SSTRIDE, bg + (size_t)i * B_GSTRIDE);
    };

    // Prologue: stages 0,1 (fresh stages, no empty-wait needed).
    load_stage(0, 0); CP_ASYNC_MBAR_ARRIVE(mb + 0 * 16);
    load_stage(1, 1); CP_ASYNC_MBAR_ARRIVE(mb + 1 * 16);

    // ---- mainloop: no __syncthreads; warps drift within ring slack ----
    for (int i = 0; i < NKT; i++) {
        const int st = i % NSTAGE;
        // consumer: wait stage filled. Stage st's (i/3)-th use -> parity.
        MBARRIER_WAIT_PARITY(mb + st * 16, (i / NSTAGE) & 1);

        const uint32_t abase = sb + (uint32_t)st * A_STAGE_B +
                               (uint32_t)(warp_m * 64 * (AROW_W * 4)) + a_toff;
        const uint32_t bbase = sb + SMEM_B0 + (uint32_t)st * B_STAGE_B +
                               (uint32_t)(warp_n * 32 * 4) + b_toff;

#pragma unroll
        for (int s = 0; s < BK / 8; s++) {          // 4 k-steps of 8
            uint32_t a[4][4];
#pragma unroll
            for (int im = 0; im < 4; im++)
                LDSM_X4(a[im], abase + (uint32_t)(im * 16 * (AROW_W * 4) + s * 32));
            uint32_t b[4][2];
#pragma unroll
            for (int jn = 0; jn < 4; jn++) {
                const uint32_t ba = bbase + (uint32_t)(jn * 32 + s * 8 * (BROW_W * 4));
                LDS32(b[jn][0], ba);
                LDS32(b[jn][1], ba + 4 * (BROW_W * 4));
            }
#pragma unroll
            for (int im = 0; im < 4; im++)
#pragma unroll
                for (int jn = 0; jn < 4; jn++)
                    MMA_TF32(acc[im][jn], a[im], b[jn]);
        }

        // release stage (one arrival per warp; release orders prior LDS)
        if (lane == 0) MBARRIER_ARRIVE(mb + st * 16 + 8);

        // producer: fetch chunk i+2 into stage (i+2)%NSTAGE
        const int cl = i + 2;
        if (cl < NKT) {
            const int s2 = cl % NSTAGE;
            if (cl >= NSTAGE) {
                // stage reuse: wait for consume of chunk cl-3 (its (cl/3)-th
                // consume overall; parity of that flip = (cl/3 - 1) & 1)
                MBARRIER_WAIT_PARITY(mb + s2 * 16 + 8, (cl / NSTAGE - 1) & 1);
            }
            load_stage(s2, cl);
            CP_ASYNC_MBAR_ARRIVE(mb + s2 * 16);
        }
    }

    // ---- epilogue: bias-cancel scale + bias, store float2 pairs ----
    const float* be = bias + (size_t)e * D_OUT + n_base + warp_n * 32;
    const int row0 = m_base + warp_m * 64 + (lane >> 2);
    const int col0 = n_base + warp_n * 32 + (lane & 3) * 2;

#pragma unroll
    for (int jn = 0; jn < 4; jn++) {
        const float2 bb = *reinterpret_cast<const float2*>(be + jn * 8 + (lane & 3) * 2);
#pragma unroll
        for (int im = 0; im < 4; im++) {
            const int r = row0 + im * 16;
            float2 v0 = make_float2(fmaf(acc[im][jn][0], OUT_SCALE, bb.x),
                                    fmaf(acc[im][jn][1], OUT_SCALE, bb.y));
            float2 v1 = make_float2(fmaf(acc[im][jn][2], OUT_SCALE, bb.x),
                                    fmaf(acc[im][jn][3], OUT_SCALE, bb.y));
            *reinterpret_cast<float2*>(out + (size_t)r * D_OUT + col0 + jn * 8) = v0;
            *reinterpret_cast<float2*>(out + (size_t)(r + 8) * D_OUT + col0 + jn * 8) = v1;
        }
    }
}

// ---------------------------------------------------------------------------
// Launch. Inputs (metadata order): sorted_tokens f32[4096,1024],
// kernel f32[8,1024,4096], bias f32[8,4096], group_sizes i32[8],
// sorted_experts i32[4096]. Output f32[4096,4096].
// ---------------------------------------------------------------------------
extern "C" void kernel_launch(void* const* d_in, const int* in_sizes, int n_in,
                              void* d_out, int out_size) {
    const float* tokens  = (const float*)d_in[0];
    const float* W       = (const float*)d_in[1];
    const float* bias    = (const float*)d_in[2];
    const int*   experts = (const int*)d_in[4];   // d_in[3] = group_sizes (unused)
    float* out = (float*)d_out;

    cudaFuncSetAttribute(moe_tf32_mma_kernel,
                         cudaFuncAttributeMaxDynamicSharedMemorySize, SMEM_TOTAL);
    dim3 grid(D_OUT / BN, T_TOK / BM);   // (32, 32)
    moe_tf32_mma_kernel<<<grid, NTHREADS, SMEM_TOTAL>>>(tokens, W, bias, experts, out);
}

// round 11
// speedup vs baseline: 1.4545x; 1.0252x over previous
#include <cuda_runtime.h>
#include <cstdint>
#include <cstddef>

// ---------------------------------------------------------------------------
// ParallelMoELinear: out[t,:] = tokens[t,:] @ W[e(t)] + bias[e(t)]
// E=8, T=4096, D_IN=1024, D_OUT=4096, 512 tokens/expert (sorted).
// sm_100 legacy tensor path (tcgen05 unavailable at this compile target).
// R11: R10 (mbarrier-skewed pipeline, 172us, tensor 72.5%) with the loop's
// scalar overhead stripped: incremental stage/parity counters (no div-by-3),
// incremental consumer/producer addresses (no per-iter IMAD chains), peeled
// first iteration and 2-iteration tail (no branches in steady state).
// alu pipe was 11.3% -- pure mbarrier/addressing overhead in a loop whose
// SMEM traffic (~128B/cyc) exactly matches the crossbar, so every stolen
// issue slot is exposed. Numerics unchanged: HW-truncated tf32 A and W with
// the combined bias cancelled by OUT_SCALE (validated R8-R10: 3.12e-4).
// ---------------------------------------------------------------------------
static constexpr int D_IN  = 1024;
static constexpr int D_OUT = 4096;
static constexpr int T_TOK = 4096;

static constexpr int BM = 128;
static constexpr int BN = 128;
static constexpr int BK = 32;
static constexpr int NSTAGE = 3;
static constexpr int NKT = D_IN / BK;       // 32
static constexpr int NTHREADS = 256;        // 8 warps: 2 (M) x 4 (N), 64x32 tiles

static constexpr float OUT_SCALE = 1.000676f;   // (1+3.38e-4)^2: A+W truncation bias

// SMEM geometry (word = 4B):
//  A tile: [BM][AROW_W], AROW_W = 36 (32 data + 4 pad)
//    -> LDSM row stride 144B == 4 mod 32 words: conflict-free ldmatrix.
//  B tile: [BK][BROW_W], BROW_W = 136 (128 data + 8 pad)
//    -> scalar B-frag banks = 8*(lane%4) + lane/4: all 32 distinct.
static constexpr int AROW_W = 36;
static constexpr int BROW_W = 136;
static constexpr uint32_t A_STAGE_B = BM * AROW_W * 4;        // 18432
static constexpr uint32_t B_STAGE_B = BK * BROW_W * 4;        // 17408
static constexpr uint32_t SMEM_B0   = NSTAGE * A_STAGE_B;     // 55296
static constexpr uint32_t SMEM_MBAR = SMEM_B0 + NSTAGE * B_STAGE_B;  // 107520
// full[s] at MBAR + s*16, empty[s] at MBAR + s*16 + 8
static constexpr uint32_t SMEM_TOTAL = SMEM_MBAR + NSTAGE * 16;      // 107568

// ---------------------------------------------------------------------------
// PTX helpers (sm_80+)
// ---------------------------------------------------------------------------
__device__ __forceinline__ uint32_t smem_to_u32(const void* p) {
    uint32_t a;
    asm("{ .reg .u64 t; cvta.to.shared.u64 t, %1; cvt.u32.u64 %0, t; }"
        : "=r"(a) : "l"(p));
    return a;
}

#define CP_ASYNC_16(dst, src) \
    asm volatile("cp.async.cg.shared.global [%0], [%1], 16;" \
        :: "r"(dst), "l"(src) : "memory")

#define CP_ASYNC_MBAR_ARRIVE(mbar) \
    asm volatile("cp.async.mbarrier.arrive.noinc.shared.b64 [%0];" \
        :: "r"((uint32_t)(mbar)) : "memory")

#define MBARRIER_INIT(mbar, count) \
    asm volatile("mbarrier.init.shared.b64 [%0], %1;" \
        :: "r"((uint32_t)(mbar)), "r"((uint32_t)(count)) : "memory")

#define MBARRIER_ARRIVE(mbar) \
    asm volatile("mbarrier.arrive.shared.b64 _, [%0];" \
        :: "r"((uint32_t)(mbar)) : "memory")

#define MBARRIER_WAIT_PARITY(mbar_smem_addr, phase_parity) do { \
    uint32_t _mbar = (uint32_t)(mbar_smem_addr); \
    uint32_t _parity = (uint32_t)(phase_parity); \
    uint32_t _done; \
    asm volatile( \
        "{\n\t.reg .pred p;\n\t" \
        "mbarrier.try_wait.parity.acquire.cta.shared::cta.b64 p, [%1], %2;\n\t" \
        "selp.b32 %0, 1, 0, p;\n\t}" \
        : "=r"(_done) : "r"(_mbar), "r"(_parity) : "memory"); \
    if (!_done) { \
        asm volatile( \
            "{\n\t.reg .pred P1;\n\t" \
            "WAIT_LOOP_%=:\n\t" \
            "mbarrier.try_wait.parity.acquire.cta.shared::cta.b64 P1, [%0], %1, 0x989680;\n\t" \
            "@P1 bra.uni WAIT_DONE_%=;\n\t" \
            "bra.uni WAIT_LOOP_%=;\n\t" \
            "WAIT_DONE_%=:\n\t}" \
            :: "r"(_mbar), "r"(_parity) : "memory"); \
    } \
} while (0)

#define LDSM_X4(r, addr) \
    asm volatile("ldmatrix.sync.aligned.m8n8.x4.shared.b16 {%0,%1,%2,%3}, [%4];" \
        : "=r"((r)[0]), "=r"((r)[1]), "=r"((r)[2]), "=r"((r)[3]) \
        : "r"(addr))

#define LDS32(r, addr) \
    asm volatile("ld.shared.b32 %0, [%1];" : "=r"(r) : "r"(addr))

#define MMA_TF32(d, a, b) \
    asm volatile( \
        "mma.sync.aligned.m16n8k8.row.col.f32.tf32.tf32.f32 " \
        "{%0,%1,%2,%3}, {%4,%5,%6,%7}, {%8,%9}, {%0,%1,%2,%3};" \
        : "+f"((d)[0]), "+f"((d)[1]), "+f"((d)[2]), "+f"((d)[3]) \
        : "r"((a)[0]), "r"((a)[1]), "r"((a)[2]), "r"((a)[3]), \
          "r"((b)[0]), "r"((b)[1]))

// ---------------------------------------------------------------------------
// GEMM kernel
// ---------------------------------------------------------------------------
__global__ void __launch_bounds__(NTHREADS, 2)
moe_tf32_mma_kernel(const float* __restrict__ tokens,
                    const float* __restrict__ W,
                    const float* __restrict__ bias,
                    const int* __restrict__ experts,
                    float* __restrict__ out) {
    extern __shared__ char smem[];
    const uint32_t sb = smem_to_u32(smem);

    const int tid  = threadIdx.x;
    const int lane = tid & 31;
    const int wid  = tid >> 5;
    const int warp_m = wid & 1;       // 2 warps in M -> 64-row warp tiles
    const int warp_n = wid >> 1;      // 4 warps in N -> 32-col warp tiles

    const int m_base = blockIdx.y * BM;
    const int n_base = blockIdx.x * BN;
    const int e = experts[m_base];    // uniform within 128-row tile (128 | 512)

    // ---- producer state: per-thread cp.async addresses, advanced by consts ----
    static constexpr int A_GSTRIDE = 32 * D_IN;          // id += 256 -> +32 rows
    static constexpr uint32_t A_SSTRIDE = 32 * AROW_W * 4;
    static constexpr int B_GSTRIDE = 8 * D_OUT;          // id += 256 -> +8 k-rows
    static constexpr uint32_t B_SSTRIDE = 8 * BROW_W * 4;

    const float* ag = tokens + (size_t)m_base * D_IN +
                      (size_t)(tid >> 3) * D_IN + (tid & 7) * 4;        // chunk 0
    const float* bg = W + (size_t)e * D_IN * D_OUT + n_base +
                      (size_t)(tid >> 5) * D_OUT + (tid & 31) * 4;      // chunk 0
    uint32_t as_p = sb + (uint32_t)((tid >> 3) * (AROW_W * 4) + (tid & 7) * 16);
    uint32_t bs_p = sb + SMEM_B0 +
                    (uint32_t)((tid >> 5) * (BROW_W * 4) + (tid & 31) * 16);

    // ---- consumer state: fragment base addresses, advanced by consts ----
    uint32_t ab = sb + (uint32_t)(warp_m * 64 * (AROW_W * 4)) +
                  (uint32_t)(((lane & 7) + ((lane >> 3) & 1) * 8) * (AROW_W * 4) +
                             (lane >> 4) * 16);
    uint32_t bb = sb + SMEM_B0 + (uint32_t)(warp_n * 32 * 4) +
                  (uint32_t)((lane & 3) * (BROW_W * 4) + (lane >> 2) * 4);

    // mbarriers: full[s] = mb + s*16 ; empty[s] = mb + s*16 + 8
    const uint32_t mb = sb + SMEM_MBAR;
    if (tid == 0) {
#pragma unroll
        for (int s = 0; s < NSTAGE; s++) {
            MBARRIER_INIT(mb + s * 16, NTHREADS);   // full: 256 cp.async arrivals
            MBARRIER_INIT(mb + s * 16 + 8, 8);      // empty: 1 per warp
        }
    }
    __syncthreads();   // init visibility (only CTA-wide barrier)

    float acc[4][4][4];
#pragma unroll
    for (int i = 0; i < 4; i++)
#pragma unroll
        for (int j = 0; j < 4; j++)
#pragma unroll
            for (int q = 0; q < 4; q++) acc[i][j][q] = 0.0f;

    auto issue_loads = [&](uint32_t as, uint32_t bs,
                           const float* a, const float* b) {
#pragma unroll
        for (int i = 0; i < 4; i++)
            CP_ASYNC_16(as + (uint32_t)i * A_SSTRIDE, a + (size_t)i * A_GSTRIDE);
#pragma unroll
        for (int i = 0; i < 4; i++)
            CP_ASYNC_16(bs + (uint32_t)i * B_SSTRIDE, b + (size_t)i * B_GSTRIDE);
    };

    auto compute_chunk = [&](uint32_t abase, uint32_t bbase) {
#pragma unroll
        for (int s = 0; s < BK / 8; s++) {          // 4 k-steps of 8
            uint32_t a[4][4];
#pragma unroll
            for (int im = 0; im < 4; im++)
                LDSM_X4(a[im], abase + (uint32_t)(im * 16 * (AROW_W * 4) + s * 32));
            uint32_t b[4][2];
#pragma unroll
            for (int jn = 0; jn < 4; jn++) {
                const uint32_t ba = bbase + (uint32_t)(jn * 32 + s * 8 * (BROW_W * 4));
                LDS32(b[jn][0], ba);
                LDS32(b[jn][1], ba + 4 * (BROW_W * 4));
            }
#pragma unroll
            for (int im = 0; im < 4; im++)
#pragma unroll
                for (int jn = 0; jn < 4; jn++)
                    MMA_TF32(acc[im][jn], a[im], b[jn]);
        }
    };

    // Incremental counters (replace all div-by-3 parity math)
    int st_c = 0, ph_c = 0;               // consumer stage / full-parity
    int st_p = 2, ph_p = 0;               // producer stage / empty-wait parity
    uint32_t as_c = 0, bs_c = 0;          // consumer stage byte offsets

    // Prologue: chunks 0,1 into stages 0,1 (fresh, no empty-wait).
    issue_loads(as_p, bs_p, ag, bg);
    CP_ASYNC_MBAR_ARRIVE(mb + 0 * 16);
    issue_loads(as_p + A_STAGE_B, bs_p + B_STAGE_B, ag + BK, bg + (size_t)BK * D_OUT);
    CP_ASYNC_MBAR_ARRIVE(mb + 1 * 16);
    ag += 2 * BK;
    bg += (size_t)2 * BK * D_OUT;

    // ---- peeled iteration 0: producer loads chunk 2 (stage 2, fresh) ----
    {
        MBARRIER_WAIT_PARITY(mb + 0 * 16, 0);
        compute_chunk(ab, bb);
        if (lane == 0) MBARRIER_ARRIVE(mb + 0 * 16 + 8);
        issue_loads(as_p + 2 * A_STAGE_B, bs_p + 2 * B_STAGE_B, ag, bg);
        CP_ASYNC_MBAR_ARRIVE(mb + 2 * 16);
        ag += BK;
        bg += (size_t)BK * D_OUT;
        st_c = 1; as_c = A_STAGE_B; bs_c = B_STAGE_B;     // advance consumer
        // producer stays: next load (chunk 3) goes to stage 0, ph_p = 0
        st_p = 0;
    }

    // ---- steady state: i = 1..29, producer loads chunk i+2 with empty-wait ----
    for (int i = 1; i < NKT - 2; i++) {
        MBARRIER_WAIT_PARITY(mb + st_c * 16, ph_c);
        compute_chunk(ab + as_c, bb + bs_c);
        if (lane == 0) MBARRIER_ARRIVE(mb + st_c * 16 + 8);

        // producer: stage st_p reuse -> wait its empty flip (parity ph_p)
        MBARRIER_WAIT_PARITY(mb + st_p * 16 + 8, ph_p);
        issue_loads(as_p + (uint32_t)st_p * A_STAGE_B,
                    bs_p + (uint32_t)st_p * B_STAGE_B, ag, bg);
        CP_ASYNC_MBAR_ARRIVE(mb + st_p * 16);
        ag += BK;
        bg += (size_t)BK * D_OUT;
        if (++st_p == NSTAGE) { st_p = 0; ph_p ^= 1; }

        // advance consumer
        as_c += A_STAGE_B; bs_c += B_STAGE_B;
        if (++st_c == NSTAGE) {
            st_c = 0; ph_c ^= 1;
            as_c = 0; bs_c = 0;
        }
    }

    // ---- tail: i = 30, 31 (no producer) ----
#pragma unroll
    for (int t = 0; t < 2; t++) {
        MBARRIER_WAIT_PARITY(mb + st_c * 16, ph_c);
        compute_chunk(ab + as_c, bb + bs_c);
        as_c += A_STAGE_B; bs_c += B_STAGE_B;
        if (++st_c == NSTAGE) {
            st_c = 0; ph_c ^= 1;
            as_c = 0; bs_c = 0;
        }
    }

    // ---- epilogue: bias-cancel scale + bias, store float2 pairs ----
    const float* be = bias + (size_t)e * D_OUT + n_base + warp_n * 32;
    const int row0 = m_base + warp_m * 64 + (lane >> 2);
    const int col0 = n_base + warp_n * 32 + (lane & 3) * 2;

#pragma unroll
    for (int jn = 0; jn < 4; jn++) {
        const float2 bb2 = *reinterpret_cast<const float2*>(be + jn * 8 + (lane & 3) * 2);
#pragma unroll
        for (int im = 0; im < 4; im++) {
            const int r = row0 + im * 16;
            float2 v0 = make_float2(fmaf(acc[im][jn][0], OUT_SCALE, bb2.x),
                                    fmaf(acc[im][jn][1], OUT_SCALE, bb2.y));
            float2 v1 = make_float2(fmaf(acc[im][jn][2], OUT_SCALE, bb2.x),
                                    fmaf(acc[im][jn][3], OUT_SCALE, bb2.y));
            *reinterpret_cast<float2*>(out + (size_t)r * D_OUT + col0 + jn * 8) = v0;
            *reinterpret_cast<float2*>(out + (size_t)(r + 8) * D_OUT + col0 + jn * 8) = v1;
        }
    }
}

// ---------------------------------------------------------------------------
// Launch. Inputs (metadata order): sorted_tokens f32[4096,1024],
// kernel f32[8,1024,4096], bias f32[8,4096], group_sizes i32[8],
// sorted_experts i32[4096]. Output f32[4096,4096].
// ---------------------------------------------------------------------------
extern "C" void kernel_launch(void* const* d_in, const int* in_sizes, int n_in,
                              void* d_out, int out_size) {
    const float* tokens  = (const float*)d_in[0];
    const float* W       = (const float*)d_in[1];
    const float* bias    = (const float*)d_in[2];
    const int*   experts = (const int*)d_in[4];   // d_in[3] = group_sizes (unused)
    float* out = (float*)d_out;

    cudaFuncSetAttribute(moe_tf32_mma_kernel,
                         cudaFuncAttributeMaxDynamicSharedMemorySize, SMEM_TOTAL);
    dim3 grid(D_OUT / BN, T_TOK / BM);   // (32, 32)
    moe_tf32_mma_kernel<<<grid, NTHREADS, SMEM_TOTAL>>>(tokens, W, bias, experts, out);
}